// round 8
// baseline (speedup 1.0000x reference)
#include <cuda_runtime.h>
#include <math.h>

// Problem constants
#define NB   2
#define NS   128
#define NROW (NB*NS)        // 256 rows (b*s)
#define NN   512            // feature dim
#define NM   1024           // 2*N output cols of GEMM
#define NK   512            // contraction dim

#define SAMPLE_ELEMS (NROW*NN)               // 131072
#define STD_ELEMS    ((long long)NROW*NN*NN) // 67108864
#define STD4         (STD_ELEMS >> 2)        // 16777216 float4

// GEMM tiling: 64x64x16, split-K=4 -> 16(N) x 4(M) x 4(K) = 256 CTAs
#define BM 64
#define BN 64
#define BK 16
#define KS 4
#define KPER (NK/KS)        // 128
#define KIT  (KPER/BK)      // 8

#define GEMM_CTAS 256
#define FILL_CTAS 256
#define FILL_THREADS (FILL_CTAS * 256)       // 65536
#define FILL_PER_TH  (STD4 / FILL_THREADS)   // 256 float4 per thread (exact)

// Scratch (no allocations allowed)
__device__ float g_part[KS * NROW * NM];   // 4 MB split-K partials

// --------- Fused: 256 GEMM CTAs + 256 PERSISTENT fill CTAs ------------------
__global__ __launch_bounds__(256)
void fused_kernel(const float* __restrict__ A, const float* __restrict__ W,
                  float* __restrict__ P, float4* __restrict__ out4) {
    const int bid = blockIdx.x;
    const int tid = threadIdx.x;

    if (bid >= GEMM_CTAS) {
        // ---- Persistent fill role: this CTA streams zeros for the whole
        //      kernel lifetime (256 float4 per thread, coalesced 512B/warp).
        const float4 z = make_float4(0.f, 0.f, 0.f, 0.f);
        long long idx = (long long)(bid - GEMM_CTAS) * 256 + tid;
        #pragma unroll 8
        for (int k = 0; k < FILL_PER_TH; k++) {
            __stcs(&out4[idx], z);
            idx += FILL_THREADS;
        }
        return;
    }

    // ---- GEMM role: split-K partial tile (64x64x16, 4x4 micro-tile) ----
    __shared__ __align__(16) float As[2][BK][BM + 4];
    __shared__ __align__(16) float Bs[2][BK][BN + 4];

    const int bx = bid & 15;          // N tile (0..15)
    const int by = (bid >> 4) & 3;    // M tile (0..3)
    const int bz = (bid >> 6) & 3;    // K split (0..3)

    const int ty = tid >> 4;          // rows ty*4..+3
    const int tx = tid & 15;          // cols tx*4..+3
    const int m0 = ty * 4;
    const int n0 = tx * 4;

    const int lrow = tid >> 2;        // 0..63
    const int lk4  = (tid & 3) << 2;  // 0,4,8,12

    const float* Ag = A + (size_t)(by * BM + lrow) * NK + bz * KPER;
    const float* Wg = W + (size_t)(bx * BN + lrow) * NK + bz * KPER;

    float acc[4][4] = {};

    // Prologue: tile 0 -> buffer 0
    float4 a4 = *(const float4*)(Ag + lk4);
    float4 w4 = *(const float4*)(Wg + lk4);
    #pragma unroll
    for (int q = 0; q < 4; q++) {
        As[0][lk4 + q][lrow] = ((const float*)&a4)[q];
        Bs[0][lk4 + q][lrow] = ((const float*)&w4)[q];
    }
    __syncthreads();

    int buf = 0;
    for (int it = 0; it < KIT; it++) {
        float4 na, nw;
        const bool more = (it + 1 < KIT);
        if (more) {
            na = *(const float4*)(Ag + (it + 1) * BK + lk4);
            nw = *(const float4*)(Wg + (it + 1) * BK + lk4);
        }

        #pragma unroll
        for (int kk = 0; kk < BK; kk++) {
            float4 av = *(const float4*)&As[buf][kk][m0];
            float4 wv = *(const float4*)&Bs[buf][kk][n0];
            #pragma unroll
            for (int i = 0; i < 4; i++) {
                float ai = ((const float*)&av)[i];
                acc[i][0] = fmaf(ai, wv.x, acc[i][0]);
                acc[i][1] = fmaf(ai, wv.y, acc[i][1]);
                acc[i][2] = fmaf(ai, wv.z, acc[i][2]);
                acc[i][3] = fmaf(ai, wv.w, acc[i][3]);
            }
        }

        if (more) {
            const int nb = buf ^ 1;
            #pragma unroll
            for (int q = 0; q < 4; q++) {
                As[nb][lk4 + q][lrow] = ((const float*)&na)[q];
                Bs[nb][lk4 + q][lrow] = ((const float*)&nw)[q];
            }
            __syncthreads();
            buf = nb;
        }
    }

    // Epilogue: split-K partials
    float* Pp = P + (size_t)bz * (NROW * NM);
    #pragma unroll
    for (int i = 0; i < 4; i++) {
        const int row = by * BM + m0 + i;
        float4 v = make_float4(acc[i][0], acc[i][1], acc[i][2], acc[i][3]);
        *(float4*)(Pp + (size_t)row * NM + bx * BN + n0) = v;
    }
}

// ---------------- Pointwise: reduce split-K + var/mu/sample + diagonal ------
__device__ __forceinline__ float softplus_f(float x) {
    return fmaxf(x, 0.0f) + log1pf(expf(-fabsf(x)));
}

__global__ __launch_bounds__(256)
void pointwise_kernel(const float* __restrict__ P,
                      const float* __restrict__ bias,
                      const float* __restrict__ eps,
                      float* __restrict__ out_sample,
                      float* __restrict__ out_mu,
                      float* __restrict__ out_std) {
    int idx = blockIdx.x * blockDim.x + threadIdx.x;
    if (idx >= SAMPLE_ELEMS) return;
    int row = idx >> 9;          // /512
    int i   = idx & (NN - 1);

    float s_var = bias[i];
    float s_mu  = bias[NN + i];
    #pragma unroll
    for (int z = 0; z < KS; z++) {
        const float* Pz = P + (size_t)z * (NROW * NM) + (size_t)row * NM;
        s_var += Pz[i];
        s_mu  += Pz[NN + i];
    }
    float var = softplus_f(s_var);
    out_mu[idx]     = s_mu;
    out_sample[idx] = fmaf(sqrtf(var), eps[idx], s_mu);
    // Diagonal scatter (zeros already laid down by fill role)
    out_std[(size_t)idx * NN + i] = var;
}

extern "C" void kernel_launch(void* const* d_in, const int* in_sizes, int n_in,
                              void* d_out, int out_size) {
    const float* x   = (const float*)d_in[0];
    const float* W   = (const float*)d_in[1];
    const float* b   = (const float*)d_in[2];
    const float* eps = (const float*)d_in[3];

    float* out        = (float*)d_out;
    float* out_sample = out;
    float* out_mu     = out + SAMPLE_ELEMS;
    float* out_std    = out + 2 * SAMPLE_ELEMS;

    float* part;  cudaGetSymbolAddress((void**)&part, g_part);

    // 1) Fused: GEMM (256 CTAs) + persistent zero-fill (256 CTAs), one wave
    fused_kernel<<<GEMM_CTAS + FILL_CTAS, 256>>>(x, W, part, (float4*)out_std);

    // 2) Pointwise: split-K reduce + sample/mu + diagonal scatter
    pointwise_kernel<<<SAMPLE_ELEMS / 256, 256>>>(part, b, eps,
                                                  out_sample, out_mu, out_std);
}

// round 9
// speedup vs baseline: 1.3618x; 1.3618x over previous
#include <cuda_runtime.h>
#include <math.h>

// Problem constants
#define NB   2
#define NS   128
#define NROW (NB*NS)        // 256 rows (b*s)
#define NN   512            // feature dim
#define NM   1024           // 2*N output cols of GEMM
#define NK   512            // contraction dim

#define SAMPLE_ELEMS (NROW*NN)               // 131072
#define STD_ELEMS    ((long long)NROW*NN*NN) // 67108864

// GEMM tiling: 64x64x16, split-K=4 -> 16(N) x 4(M) x 4(K) = 256 CTAs
#define BM 64
#define BN 64
#define BK 16
#define KS 4
#define KPER (NK/KS)        // 128
#define KIT  (KPER/BK)      // 8

// Scratch (no allocations allowed)
__device__ float g_part[KS * NROW * NM];   // 4 MB split-K partials
__device__ float g_var[NROW * NN];         // 0.5 MB softplus(var) buffer

// ---------------- Split-K GEMM: 4x4 micro-tile, double-buffered -------------
__global__ __launch_bounds__(256)
void gemm_kernel(const float* __restrict__ A, const float* __restrict__ W,
                 float* __restrict__ P) {
    __shared__ __align__(16) float As[2][BK][BM + 4];
    __shared__ __align__(16) float Bs[2][BK][BN + 4];

    const int tid = threadIdx.x;
    const int bx = blockIdx.x & 15;         // N tile (0..15)
    const int by = (blockIdx.x >> 4) & 3;   // M tile (0..3)
    const int bz = blockIdx.x >> 6;         // K split (0..3)

    const int ty = tid >> 4;                // rows ty*4..+3
    const int tx = tid & 15;                // cols tx*4..+3
    const int m0 = ty * 4;
    const int n0 = tx * 4;

    const int lrow = tid >> 2;              // 0..63
    const int lk4  = (tid & 3) << 2;        // 0,4,8,12

    const float* Ag = A + (size_t)(by * BM + lrow) * NK + bz * KPER;
    const float* Wg = W + (size_t)(bx * BN + lrow) * NK + bz * KPER;

    float acc[4][4] = {};

    // Prologue: tile 0 -> buffer 0
    float4 a4 = *(const float4*)(Ag + lk4);
    float4 w4 = *(const float4*)(Wg + lk4);
    #pragma unroll
    for (int q = 0; q < 4; q++) {
        As[0][lk4 + q][lrow] = ((const float*)&a4)[q];
        Bs[0][lk4 + q][lrow] = ((const float*)&w4)[q];
    }
    __syncthreads();

    int buf = 0;
    for (int it = 0; it < KIT; it++) {
        float4 na, nw;
        const bool more = (it + 1 < KIT);
        if (more) {
            na = *(const float4*)(Ag + (it + 1) * BK + lk4);
            nw = *(const float4*)(Wg + (it + 1) * BK + lk4);
        }

        #pragma unroll
        for (int kk = 0; kk < BK; kk++) {
            float4 av = *(const float4*)&As[buf][kk][m0];
            float4 wv = *(const float4*)&Bs[buf][kk][n0];
            #pragma unroll
            for (int i = 0; i < 4; i++) {
                float ai = ((const float*)&av)[i];
                acc[i][0] = fmaf(ai, wv.x, acc[i][0]);
                acc[i][1] = fmaf(ai, wv.y, acc[i][1]);
                acc[i][2] = fmaf(ai, wv.z, acc[i][2]);
                acc[i][3] = fmaf(ai, wv.w, acc[i][3]);
            }
        }

        if (more) {
            const int nb = buf ^ 1;
            #pragma unroll
            for (int q = 0; q < 4; q++) {
                As[nb][lk4 + q][lrow] = ((const float*)&na)[q];
                Bs[nb][lk4 + q][lrow] = ((const float*)&nw)[q];
            }
            __syncthreads();
            buf = nb;
        }
    }

    // Epilogue: split-K partials
    float* Pp = P + (size_t)bz * (NROW * NM);
    #pragma unroll
    for (int i = 0; i < 4; i++) {
        const int row = by * BM + m0 + i;
        float4 v = make_float4(acc[i][0], acc[i][1], acc[i][2], acc[i][3]);
        *(float4*)(Pp + (size_t)row * NM + bx * BN + n0) = v;
    }
}

// ---------------- Pointwise: reduce split-K + var/mu/sample ----------------
__device__ __forceinline__ float softplus_f(float x) {
    return fmaxf(x, 0.0f) + log1pf(expf(-fabsf(x)));
}

__global__ __launch_bounds__(256)
void pointwise_kernel(const float* __restrict__ P,
                      const float* __restrict__ bias,
                      const float* __restrict__ eps,
                      float* __restrict__ out_sample,
                      float* __restrict__ out_mu,
                      float* __restrict__ var_buf) {
    int idx = blockIdx.x * blockDim.x + threadIdx.x;
    if (idx >= SAMPLE_ELEMS) return;
    int row = idx >> 9;          // /512
    int i   = idx & (NN - 1);

    float s_var = bias[i];
    float s_mu  = bias[NN + i];
    #pragma unroll
    for (int z = 0; z < KS; z++) {
        const float* Pz = P + (size_t)z * (NROW * NM) + (size_t)row * NM;
        s_var += Pz[i];
        s_mu  += Pz[NN + i];
    }
    float var = softplus_f(s_var);
    var_buf[idx]    = var;
    out_mu[idx]     = s_mu;
    out_sample[idx] = fmaf(sqrtf(var), eps[idx], s_mu);
}

// ---------------- Fill std_mat: zeros + diagonal in ONE streaming pass ------
__global__ __launch_bounds__(256)
void fill_std_kernel(const float* __restrict__ var_buf, float4* __restrict__ out4) {
    const long long total4 = STD_ELEMS >> 2;   // 16777216 float4
    long long idx = (long long)blockIdx.x * blockDim.x + threadIdx.x;
    const long long stride = (long long)gridDim.x * blockDim.x;
    for (; idx < total4; idx += stride) {
        long long j = idx << 2;                // float index
        int r  = (int)(j >> 9);                // global row (0 .. 131071)
        int cs = (int)(j & (NN - 1));          // col start of this float4
        int d  = (r & (NN - 1)) - cs;          // diag offset within this float4
        float4 v = make_float4(0.f, 0.f, 0.f, 0.f);
        if ((unsigned)d < 4u) {
            float vv = var_buf[r];
            if      (d == 0) v.x = vv;
            else if (d == 1) v.y = vv;
            else if (d == 2) v.z = vv;
            else             v.w = vv;
        }
        __stcs(&out4[idx], v);   // evict-streaming full-line stores
    }
}

extern "C" void kernel_launch(void* const* d_in, const int* in_sizes, int n_in,
                              void* d_out, int out_size) {
    const float* x   = (const float*)d_in[0];
    const float* W   = (const float*)d_in[1];
    const float* b   = (const float*)d_in[2];
    const float* eps = (const float*)d_in[3];

    float* out        = (float*)d_out;
    float* out_sample = out;
    float* out_mu     = out + SAMPLE_ELEMS;
    float* out_std    = out + 2 * SAMPLE_ELEMS;

    float* part;  cudaGetSymbolAddress((void**)&part, g_part);
    float* varb;  cudaGetSymbolAddress((void**)&varb, g_var);

    // 1) Split-K GEMM -> partials (256 CTAs, 13.2us measured)
    gemm_kernel<<<16 * 4 * KS, 256>>>(x, W, part);

    // 2) Pointwise: reduce + sample/mu + var_buf (no scatter)
    pointwise_kernel<<<SAMPLE_ELEMS / 256, 256>>>(part, b, eps,
                                                  out_sample, out_mu, varb);

    // 3) Single-pass fill: zeros + diagonal (DRAM roofline stream)
    fill_std_kernel<<<8192, 256>>>(varb, (float4*)out_std);
}

// round 11
// speedup vs baseline: 1.3706x; 1.0064x over previous
#include <cuda_runtime.h>
#include <math.h>

// Problem constants
#define NB   2
#define NS   128
#define NROW (NB*NS)        // 256 rows (b*s)
#define NN   512            // feature dim
#define NM   1024           // 2*N output cols of GEMM
#define NK   512            // contraction dim

#define SAMPLE_ELEMS (NROW*NN)               // 131072
#define STD_ELEMS    ((long long)NROW*NN*NN) // 67108864

// GEMM tiling: 64x64x16, split-K=8 -> 16(N) x 4(M) x 8(K) = 512 CTAs
#define BM 64
#define BN 64
#define BK 16
#define KS 8
#define KPER (NK/KS)        // 64
#define KIT  (KPER/BK)      // 4

// Scratch (no allocations allowed)
__device__ float g_part[KS * NROW * NM];   // 8 MB split-K partials
__device__ float g_var[NROW * NN];         // 0.5 MB softplus(var) buffer

// ---------------- Split-K GEMM: 4x4 micro-tile, double-buffered -------------
__global__ __launch_bounds__(256)
void gemm_kernel(const float* __restrict__ A, const float* __restrict__ W,
                 float* __restrict__ P) {
    __shared__ __align__(16) float As[2][BK][BM + 4];
    __shared__ __align__(16) float Bs[2][BK][BN + 4];

    const int tid = threadIdx.x;
    const int bx = blockIdx.x & 15;         // N tile (0..15)
    const int by = (blockIdx.x >> 4) & 3;   // M tile (0..3)
    const int bz = blockIdx.x >> 6;         // K split (0..7)

    const int ty = tid >> 4;                // rows ty*4..+3
    const int tx = tid & 15;                // cols tx*4..+3
    const int m0 = ty * 4;
    const int n0 = tx * 4;

    const int lrow = tid >> 2;              // 0..63
    const int lk4  = (tid & 3) << 2;        // 0,4,8,12

    const float* Ag = A + (size_t)(by * BM + lrow) * NK + bz * KPER;
    const float* Wg = W + (size_t)(bx * BN + lrow) * NK + bz * KPER;

    float acc[4][4] = {};

    // Prologue: tile 0 -> buffer 0
    float4 a4 = *(const float4*)(Ag + lk4);
    float4 w4 = *(const float4*)(Wg + lk4);
    #pragma unroll
    for (int q = 0; q < 4; q++) {
        As[0][lk4 + q][lrow] = ((const float*)&a4)[q];
        Bs[0][lk4 + q][lrow] = ((const float*)&w4)[q];
    }
    __syncthreads();

    int buf = 0;
    for (int it = 0; it < KIT; it++) {
        float4 na, nw;
        const bool more = (it + 1 < KIT);
        if (more) {
            na = *(const float4*)(Ag + (it + 1) * BK + lk4);
            nw = *(const float4*)(Wg + (it + 1) * BK + lk4);
        }

        #pragma unroll
        for (int kk = 0; kk < BK; kk++) {
            float4 av = *(const float4*)&As[buf][kk][m0];
            float4 wv = *(const float4*)&Bs[buf][kk][n0];
            #pragma unroll
            for (int i = 0; i < 4; i++) {
                float ai = ((const float*)&av)[i];
                acc[i][0] = fmaf(ai, wv.x, acc[i][0]);
                acc[i][1] = fmaf(ai, wv.y, acc[i][1]);
                acc[i][2] = fmaf(ai, wv.z, acc[i][2]);
                acc[i][3] = fmaf(ai, wv.w, acc[i][3]);
            }
        }

        if (more) {
            const int nb = buf ^ 1;
            #pragma unroll
            for (int q = 0; q < 4; q++) {
                As[nb][lk4 + q][lrow] = ((const float*)&na)[q];
                Bs[nb][lk4 + q][lrow] = ((const float*)&nw)[q];
            }
            __syncthreads();
            buf = nb;
        }
    }

    // Epilogue: split-K partials
    float* Pp = P + (size_t)bz * (NROW * NM);
    #pragma unroll
    for (int i = 0; i < 4; i++) {
        const int row = by * BM + m0 + i;
        float4 v = make_float4(acc[i][0], acc[i][1], acc[i][2], acc[i][3]);
        *(float4*)(Pp + (size_t)row * NM + bx * BN + n0) = v;
    }
}

// ---------------- Pointwise: reduce split-K + var/mu/sample (float2) --------
__device__ __forceinline__ float softplus_f(float x) {
    return fmaxf(x, 0.0f) + log1pf(expf(-fabsf(x)));
}

__global__ __launch_bounds__(256)
void pointwise_kernel(const float* __restrict__ P,
                      const float* __restrict__ bias,
                      const float* __restrict__ eps,
                      float2* __restrict__ out_sample,
                      float2* __restrict__ out_mu,
                      float2* __restrict__ var_buf) {
    int t = blockIdx.x * blockDim.x + threadIdx.x;   // 0 .. 65535 (float2 units)
    if (t >= SAMPLE_ELEMS / 2) return;
    int row = t >> 8;                 // /256 float2 per row
    int i2  = t & 255;                // float2 col index

    float2 sv = ((const float2*)bias)[i2];
    float2 sm = ((const float2*)bias)[(NN >> 1) + i2];
    #pragma unroll
    for (int z = 0; z < KS; z++) {
        const float2* Pz = (const float2*)(P + (size_t)z * (NROW * NM) + (size_t)row * NM);
        float2 pv = Pz[i2];
        float2 pm = Pz[(NN >> 1) + i2];
        sv.x += pv.x; sv.y += pv.y;
        sm.x += pm.x; sm.y += pm.y;
    }

    float2 var;
    var.x = softplus_f(sv.x);
    var.y = softplus_f(sv.y);

    float2 ep = ((const float2*)eps)[t];
    float2 smp;
    smp.x = fmaf(sqrtf(var.x), ep.x, sm.x);
    smp.y = fmaf(sqrtf(var.y), ep.y, sm.y);

    var_buf[t]    = var;
    out_mu[t]     = sm;
    out_sample[t] = smp;
}

// ---------------- Fill std_mat: zeros + diagonal in ONE streaming pass ------
__global__ __launch_bounds__(256)
void fill_std_kernel(const float* __restrict__ var_buf, float4* __restrict__ out4) {
    const long long total4 = STD_ELEMS >> 2;   // 16777216 float4
    long long idx = (long long)blockIdx.x * blockDim.x + threadIdx.x;
    const long long stride = (long long)gridDim.x * blockDim.x;
    for (; idx < total4; idx += stride) {
        long long j = idx << 2;                // float index
        int r  = (int)(j >> 9);                // global row (0 .. 131071)
        int cs = (int)(j & (NN - 1));          // col start of this float4
        int d  = (r & (NN - 1)) - cs;          // diag offset within this float4
        float4 v = make_float4(0.f, 0.f, 0.f, 0.f);
        if ((unsigned)d < 4u) {
            float vv = var_buf[r];
            if      (d == 0) v.x = vv;
            else if (d == 1) v.y = vv;
            else if (d == 2) v.z = vv;
            else             v.w = vv;
        }
        __stcs(&out4[idx], v);   // evict-streaming full-line stores
    }
}

extern "C" void kernel_launch(void* const* d_in, const int* in_sizes, int n_in,
                              void* d_out, int out_size) {
    const float* x   = (const float*)d_in[0];
    const float* W   = (const float*)d_in[1];
    const float* b   = (const float*)d_in[2];
    const float* eps = (const float*)d_in[3];

    float* out        = (float*)d_out;
    float* out_sample = out;
    float* out_mu     = out + SAMPLE_ELEMS;
    float* out_std    = out + 2 * SAMPLE_ELEMS;

    float* part;  cudaGetSymbolAddress((void**)&part, g_part);
    float* varb;  cudaGetSymbolAddress((void**)&varb, g_var);

    // 1) Split-K=8 GEMM -> partials (512 CTAs, ~3.5/SM)
    gemm_kernel<<<16 * 4 * KS, 256>>>(x, W, part);

    // 2) Pointwise: reduce + sample/mu + var_buf (float2, L2-hot partials)
    pointwise_kernel<<<(SAMPLE_ELEMS / 2) / 256, 256>>>(part, b, eps,
                                                        (float2*)out_sample,
                                                        (float2*)out_mu,
                                                        (float2*)varb);

    // 3) Single-pass fill: zeros + diagonal (DRAM roofline stream)
    fill_std_kernel<<<8192, 256>>>(varb, (float4*)out_std);
}

// round 12
// speedup vs baseline: 1.3957x; 1.0184x over previous
#include <cuda_runtime.h>
#include <math.h>

// Problem constants
#define NB   2
#define NS   128
#define NROW (NB*NS)        // 256 rows (b*s)
#define NN   512            // feature dim
#define NM   1024           // 2*N output cols of GEMM
#define NK   512            // contraction dim

#define SAMPLE_ELEMS (NROW*NN)               // 131072
#define STD_ELEMS    ((long long)NROW*NN*NN) // 67108864

// GEMM tiling: 128x64x16, 8x4 micro-tile, split-K=8 -> 16 x 2 x 8 = 256 CTAs
#define BM 128
#define BN 64
#define BK 16
#define KS 8
#define KPER (NK/KS)        // 64
#define KIT  (KPER/BK)      // 4

// Scratch (no allocations allowed)
__device__ float g_part[KS * NROW * NM];   // 8 MB split-K partials
__device__ float g_var[NROW * NN];         // 0.5 MB softplus(var) buffer

// ---------------- Split-K GEMM: 8x4 micro-tile, double-buffered -------------
__global__ __launch_bounds__(256)
void gemm_kernel(const float* __restrict__ A, const float* __restrict__ W,
                 float* __restrict__ P) {
    __shared__ __align__(16) float As[2][BK][BM + 4];
    __shared__ __align__(16) float Bs[2][BK][BN + 4];

    const int tid = threadIdx.x;
    const int bx = blockIdx.x & 15;         // N tile (0..15)
    const int by = (blockIdx.x >> 4) & 1;   // M tile (0..1)
    const int bz = blockIdx.x >> 5;         // K split (0..7)

    const int ty = tid >> 4;                // 0..15 -> rows ty*8..+7
    const int tx = tid & 15;                // cols tx*4..+3
    const int m0 = ty * 8;
    const int n0 = tx * 4;

    // A loads: 512 float4 per stage, 2 per thread
    const int arow0 = tid >> 1;                   // 0..127
    const int ak0   = (tid & 1) << 3;             // 0 or 8 (float offset)
    // B loads: 256 float4 per stage, 1 per thread
    const int brow  = tid >> 2;                   // 0..63
    const int bk4   = (tid & 3) << 2;             // 0,4,8,12

    const float* Ag = A + (size_t)(by * BM + arow0) * NK + bz * KPER + ak0;
    const float* Wg = W + (size_t)(bx * BN + brow) * NK + bz * KPER + bk4;

    float acc[8][4] = {};

    // Prologue: tile 0 -> buffer 0
    {
        float4 a0 = *(const float4*)(Ag);
        float4 a1 = *(const float4*)(Ag + 4);
        float4 w0 = *(const float4*)(Wg);
        #pragma unroll
        for (int q = 0; q < 4; q++) {
            As[0][ak0 + q][arow0]     = ((const float*)&a0)[q];
            As[0][ak0 + 4 + q][arow0] = ((const float*)&a1)[q];
            Bs[0][bk4 + q][brow]      = ((const float*)&w0)[q];
        }
    }
    __syncthreads();

    int buf = 0;
    for (int it = 0; it < KIT; it++) {
        float4 na0, na1, nw0;
        const bool more = (it + 1 < KIT);
        if (more) {
            na0 = *(const float4*)(Ag + (it + 1) * BK);
            na1 = *(const float4*)(Ag + (it + 1) * BK + 4);
            nw0 = *(const float4*)(Wg + (it + 1) * BK);
        }

        #pragma unroll
        for (int kk = 0; kk < BK; kk++) {
            float4 avlo = *(const float4*)&As[buf][kk][m0];
            float4 avhi = *(const float4*)&As[buf][kk][m0 + 4];
            float4 wv   = *(const float4*)&Bs[buf][kk][n0];
            #pragma unroll
            for (int i = 0; i < 4; i++) {
                float ai = ((const float*)&avlo)[i];
                acc[i][0] = fmaf(ai, wv.x, acc[i][0]);
                acc[i][1] = fmaf(ai, wv.y, acc[i][1]);
                acc[i][2] = fmaf(ai, wv.z, acc[i][2]);
                acc[i][3] = fmaf(ai, wv.w, acc[i][3]);
            }
            #pragma unroll
            for (int i = 0; i < 4; i++) {
                float ai = ((const float*)&avhi)[i];
                acc[4 + i][0] = fmaf(ai, wv.x, acc[4 + i][0]);
                acc[4 + i][1] = fmaf(ai, wv.y, acc[4 + i][1]);
                acc[4 + i][2] = fmaf(ai, wv.z, acc[4 + i][2]);
                acc[4 + i][3] = fmaf(ai, wv.w, acc[4 + i][3]);
            }
        }

        if (more) {
            const int nb = buf ^ 1;
            #pragma unroll
            for (int q = 0; q < 4; q++) {
                As[nb][ak0 + q][arow0]     = ((const float*)&na0)[q];
                As[nb][ak0 + 4 + q][arow0] = ((const float*)&na1)[q];
                Bs[nb][bk4 + q][brow]      = ((const float*)&nw0)[q];
            }
            __syncthreads();
            buf = nb;
        }
    }

    // Epilogue: split-K partials
    float* Pp = P + (size_t)bz * (NROW * NM);
    #pragma unroll
    for (int i = 0; i < 8; i++) {
        const int row = by * BM + m0 + i;
        float4 v = make_float4(acc[i][0], acc[i][1], acc[i][2], acc[i][3]);
        *(float4*)(Pp + (size_t)row * NM + bx * BN + n0) = v;
    }
}

// ---------------- Pointwise: reduce split-K + var/mu/sample (float2) --------
__device__ __forceinline__ float softplus_f(float x) {
    return fmaxf(x, 0.0f) + log1pf(expf(-fabsf(x)));
}

__global__ __launch_bounds__(256)
void pointwise_kernel(const float* __restrict__ P,
                      const float* __restrict__ bias,
                      const float* __restrict__ eps,
                      float2* __restrict__ out_sample,
                      float2* __restrict__ out_mu,
                      float2* __restrict__ var_buf) {
    int t = blockIdx.x * blockDim.x + threadIdx.x;   // 0 .. 65535 (float2 units)
    if (t >= SAMPLE_ELEMS / 2) return;
    int row = t >> 8;                 // /256 float2 per row
    int i2  = t & 255;                // float2 col index

    float2 sv = ((const float2*)bias)[i2];
    float2 sm = ((const float2*)bias)[(NN >> 1) + i2];
    #pragma unroll
    for (int z = 0; z < KS; z++) {
        const float2* Pz = (const float2*)(P + (size_t)z * (NROW * NM) + (size_t)row * NM);
        float2 pv = Pz[i2];
        float2 pm = Pz[(NN >> 1) + i2];
        sv.x += pv.x; sv.y += pv.y;
        sm.x += pm.x; sm.y += pm.y;
    }

    float2 var;
    var.x = softplus_f(sv.x);
    var.y = softplus_f(sv.y);

    float2 ep = ((const float2*)eps)[t];
    float2 smp;
    smp.x = fmaf(sqrtf(var.x), ep.x, sm.x);
    smp.y = fmaf(sqrtf(var.y), ep.y, sm.y);

    var_buf[t]    = var;
    out_mu[t]     = sm;
    out_sample[t] = smp;
}

// ---------------- Fill std_mat: zeros + diagonal in ONE streaming pass ------
__global__ __launch_bounds__(256)
void fill_std_kernel(const float* __restrict__ var_buf, float4* __restrict__ out4) {
    const long long total4 = STD_ELEMS >> 2;   // 16777216 float4
    long long idx = (long long)blockIdx.x * blockDim.x + threadIdx.x;
    const long long stride = (long long)gridDim.x * blockDim.x;
    for (; idx < total4; idx += stride) {
        long long j = idx << 2;                // float index
        int r  = (int)(j >> 9);                // global row (0 .. 131071)
        int cs = (int)(j & (NN - 1));          // col start of this float4
        int d  = (r & (NN - 1)) - cs;          // diag offset within this float4
        float4 v = make_float4(0.f, 0.f, 0.f, 0.f);
        if ((unsigned)d < 4u) {
            float vv = var_buf[r];
            if      (d == 0) v.x = vv;
            else if (d == 1) v.y = vv;
            else if (d == 2) v.z = vv;
            else             v.w = vv;
        }
        __stcs(&out4[idx], v);   // evict-streaming full-line stores
    }
}

extern "C" void kernel_launch(void* const* d_in, const int* in_sizes, int n_in,
                              void* d_out, int out_size) {
    const float* x   = (const float*)d_in[0];
    const float* W   = (const float*)d_in[1];
    const float* b   = (const float*)d_in[2];
    const float* eps = (const float*)d_in[3];

    float* out        = (float*)d_out;
    float* out_sample = out;
    float* out_mu     = out + SAMPLE_ELEMS;
    float* out_std    = out + 2 * SAMPLE_ELEMS;

    float* part;  cudaGetSymbolAddress((void**)&part, g_part);
    float* varb;  cudaGetSymbolAddress((void**)&varb, g_var);

    // 1) Split-K=8 GEMM -> partials (256 CTAs, 8x4 micro-tile)
    gemm_kernel<<<16 * 2 * KS, 256>>>(x, W, part);

    // 2) Pointwise: reduce + sample/mu + var_buf (float2, L2-hot partials)
    pointwise_kernel<<<(SAMPLE_ELEMS / 2) / 256, 256>>>(part, b, eps,
                                                        (float2*)out_sample,
                                                        (float2*)out_mu,
                                                        (float2*)varb);

    // 3) Single-pass fill: zeros + diagonal (DRAM roofline stream)
    fill_std_kernel<<<8192, 256>>>(varb, (float4*)out_std);
}